// round 1
// baseline (speedup 1.0000x reference)
#include <cuda_runtime.h>

#define NNODES 100000
#define NEDGES 1000000
#define NGRAPHS 1000
#define EMBED 64
#define OUTDIM 128
#define NCONV 3
#define BN_EPS 1e-5f

// ---------------- scratch (no allocs allowed) ----------------
__device__ float d_h[NNODES * EMBED];      // node features (updated in place per layer)
__device__ float d_t[NNODES * EMBED];      // agg + h (GEMM input)
__device__ float d_y[NNODES * EMBED];      // GEMM output (pre-BN)
__device__ int   d_deg[NNODES];
__device__ int   d_rowptr[NNODES + 1];
__device__ int   d_cursor[NNODES];
__device__ unsigned d_edge[NEDGES];        // packed: src (17 bits) | efeat << 17
__device__ float d_stats[NCONV * 2 * EMBED];  // per-layer [sum(64), sumsq(64)]
__device__ float d_gn[NGRAPHS * EMBED];

// ---------------- setup kernels ----------------
__global__ void k_zero() {
    int i = blockIdx.x * blockDim.x + threadIdx.x;
    if (i < NNODES) d_deg[i] = 0;
    if (i < NCONV * 2 * EMBED) d_stats[i] = 0.f;
}

__global__ void k_embed(const int* __restrict__ nfeat,
                        const float4* __restrict__ atom_embed) {
    int i = blockIdx.x * blockDim.x + threadIdx.x;   // float4 granularity
    if (i >= NNODES * (EMBED / 4)) return;
    int n = i >> 4;          // 16 float4 per row
    int c4 = i & 15;
    ((float4*)d_h)[i] = atom_embed[nfeat[n] * 16 + c4];
}

__global__ void k_count(const int* __restrict__ dst) {
    int e = blockIdx.x * blockDim.x + threadIdx.x;
    if (e < NEDGES) atomicAdd(&d_deg[dst[e]], 1);
}

// single-block exclusive scan over deg -> rowptr, also primes cursor
__global__ void k_scan() {
    __shared__ int s[1024];
    int t = threadIdx.x;
    const int chunk = (NNODES + 1023) / 1024;  // 98
    int lo = t * chunk;
    int hi = lo + chunk; if (hi > NNODES) hi = NNODES;
    if (lo > NNODES) lo = NNODES;
    int sum = 0;
    for (int i = lo; i < hi; i++) sum += d_deg[i];
    s[t] = sum;
    __syncthreads();
    // Hillis-Steele inclusive scan
    for (int off = 1; off < 1024; off <<= 1) {
        int v = (t >= off) ? s[t - off] : 0;
        __syncthreads();
        s[t] += v;
        __syncthreads();
    }
    int run = (t > 0) ? s[t - 1] : 0;   // exclusive prefix
    for (int i = lo; i < hi; i++) {
        d_rowptr[i] = run;
        d_cursor[i] = run;
        run += d_deg[i];
    }
    if (t == 1023) d_rowptr[NNODES] = s[1023];
}

__global__ void k_fill(const int* __restrict__ src,
                       const int* __restrict__ efeat,
                       const int* __restrict__ dst) {
    int e = blockIdx.x * blockDim.x + threadIdx.x;
    if (e >= NEDGES) return;
    int p = atomicAdd(&d_cursor[dst[e]], 1);
    d_edge[p] = (unsigned)src[e] | ((unsigned)efeat[e] << 17);
}

// ---------------- per-layer kernels ----------------
// warp per node: t[n] = mean_{e: dst=n} relu(bond[efeat] + h[src]) + h[n]
__global__ void k_msg(const float* __restrict__ bond) {  // bond: [5,64] slice
    __shared__ __align__(16) float bsh[5 * EMBED];
    int tid = threadIdx.x;
    for (int i = tid; i < 5 * EMBED; i += blockDim.x) bsh[i] = bond[i];
    __syncthreads();
    int warp = tid >> 5, lane = tid & 31;
    int node = blockIdx.x * 8 + warp;
    if (node >= NNODES) return;
    int rs = d_rowptr[node], re = d_rowptr[node + 1];
    float ax = 0.f, ay = 0.f;
    for (int e = rs; e < re; e++) {
        unsigned p = d_edge[e];
        int s = (int)(p & 131071u);
        int ef = (int)(p >> 17);
        float2 he = ((const float2*)(bsh + ef * EMBED))[lane];
        float2 hs = ((const float2*)(d_h + (size_t)s * EMBED))[lane];
        ax += fmaxf(he.x + hs.x, 0.f);
        ay += fmaxf(he.y + hs.y, 0.f);
    }
    int deg = re - rs;
    float inv = 1.f / (float)(deg > 0 ? deg : 1);
    float2 hn = ((const float2*)(d_h + (size_t)node * EMBED))[lane];
    float2 o;
    o.x = ax * inv + hn.x;
    o.y = ay * inv + hn.y;
    ((float2*)(d_t + (size_t)node * EMBED))[lane] = o;
}

// thread per node: y = t @ W + b  (W in shared, t row in registers)
__global__ void k_gemm(const float* __restrict__ W, const float* __restrict__ b) {
    __shared__ float Ws[EMBED * EMBED];
    int tid = threadIdx.x;
    #pragma unroll
    for (int i = tid; i < EMBED * EMBED; i += 256) Ws[i] = W[i];
    __syncthreads();
    int node = blockIdx.x * 256 + tid;
    if (node >= NNODES) return;
    float tr[EMBED];
    const float4* tp = (const float4*)(d_t + (size_t)node * EMBED);
    #pragma unroll
    for (int i = 0; i < 16; i++) {
        float4 v = tp[i];
        tr[4 * i] = v.x; tr[4 * i + 1] = v.y; tr[4 * i + 2] = v.z; tr[4 * i + 3] = v.w;
    }
    #pragma unroll 4
    for (int c = 0; c < EMBED; c++) {
        float acc = b[c];
        #pragma unroll
        for (int k = 0; k < EMBED; k++) acc += tr[k] * Ws[k * EMBED + c];
        d_y[(size_t)node * EMBED + c] = acc;
    }
}

// per-channel sum / sumsq over all nodes
__global__ void k_stats(int layer) {
    __shared__ float ssum[256], ssq[256];
    int tid = threadIdx.x;
    int c = tid & 63, grp = tid >> 6;   // 4 row-groups per block
    float sum = 0.f, sq = 0.f;
    for (int row = blockIdx.x * 4 + grp; row < NNODES; row += gridDim.x * 4) {
        float v = d_y[(size_t)row * EMBED + c];
        sum += v; sq += v * v;
    }
    ssum[tid] = sum; ssq[tid] = sq;
    __syncthreads();
    if (grp == 0) {
        sum = ssum[c] + ssum[64 + c] + ssum[128 + c] + ssum[192 + c];
        sq  = ssq[c]  + ssq[64 + c]  + ssq[128 + c]  + ssq[192 + c];
        atomicAdd(&d_stats[layer * 128 + c], sum);
        atomicAdd(&d_stats[layer * 128 + 64 + c], sq);
    }
}

// normalize + gamma/beta + optional relu + residual (h += act)
__global__ void k_bn(int layer, const float* __restrict__ gamma,
                     const float* __restrict__ beta, int do_relu) {
    int i = blockIdx.x * blockDim.x + threadIdx.x;
    if (i >= NNODES * EMBED) return;
    int c = i & 63;
    const float* st = d_stats + layer * 128;
    const float invN = 1.f / (float)NNODES;
    float mu = st[c] * invN;
    float var = st[64 + c] * invN - mu * mu;
    float rs = rsqrtf(fmaxf(var, 0.f) + BN_EPS);
    float v = (d_y[i] - mu) * rs * gamma[c] + beta[c];
    if (do_relu) v = fmaxf(v, 0.f);
    d_h[i] += v;
}

// ---------------- tail kernels ----------------
// block per graph; graph_ids sorted -> binary search range
__global__ void k_pool(const int* __restrict__ gids) {
    int g = blockIdx.x, c = threadIdx.x;
    int lo = 0, hi = NNODES;
    while (lo < hi) { int m = (lo + hi) >> 1; if (gids[m] < g) lo = m + 1; else hi = m; }
    int start = lo;
    hi = NNODES;
    while (lo < hi) { int m = (lo + hi) >> 1; if (gids[m] < g + 1) lo = m + 1; else hi = m; }
    int end = lo;
    float acc = 0.f;
    for (int n = start; n < end; n++) acc += d_h[(size_t)n * EMBED + c];
    int cnt = end - start;
    d_gn[g * EMBED + c] = acc / (float)(cnt > 0 ? cnt : 1);
}

__global__ void k_pred(const float* __restrict__ W, const float* __restrict__ b,
                       float* __restrict__ out) {
    __shared__ float gs[EMBED];
    int g = blockIdx.x, o = threadIdx.x;
    if (o < EMBED) gs[o] = d_gn[g * EMBED + o];
    __syncthreads();
    float acc = b[o];
    #pragma unroll
    for (int k = 0; k < EMBED; k++) acc += gs[k] * W[k * OUTDIM + o];
    out[g * OUTDIM + o] = acc;
}

// ---------------- launch ----------------
extern "C" void kernel_launch(void* const* d_in, const int* in_sizes, int n_in,
                              void* d_out, int out_size) {
    const int*   nfeat      = (const int*)d_in[0];
    const int*   efeat      = (const int*)d_in[1];
    const int*   src        = (const int*)d_in[2];
    const int*   dst        = (const int*)d_in[3];
    const int*   gids       = (const int*)d_in[4];
    const float* atom_embed = (const float*)d_in[5];
    const float* bond_embed = (const float*)d_in[6];
    const float* conv_W     = (const float*)d_in[7];
    const float* conv_b     = (const float*)d_in[8];
    const float* bn_gamma   = (const float*)d_in[9];
    const float* bn_beta    = (const float*)d_in[10];
    const float* pred_W     = (const float*)d_in[11];
    const float* pred_b     = (const float*)d_in[12];
    float* out = (float*)d_out;

    k_zero<<<(NNODES + 255) / 256, 256>>>();
    k_embed<<<(NNODES * 16 + 255) / 256, 256>>>(nfeat, (const float4*)atom_embed);
    k_count<<<(NEDGES + 255) / 256, 256>>>(dst);
    k_scan<<<1, 1024>>>();
    k_fill<<<(NEDGES + 255) / 256, 256>>>(src, efeat, dst);

    for (int i = 0; i < NCONV; i++) {
        k_msg<<<(NNODES + 7) / 8, 256>>>(bond_embed + i * 5 * EMBED);
        k_gemm<<<(NNODES + 255) / 256, 256>>>(conv_W + i * EMBED * EMBED,
                                              conv_b + i * EMBED);
        k_stats<<<256, 256>>>(i);
        k_bn<<<(NNODES * EMBED + 255) / 256, 256>>>(i, bn_gamma + i * EMBED,
                                                    bn_beta + i * EMBED,
                                                    (i < NCONV - 1) ? 1 : 0);
    }

    k_pool<<<NGRAPHS, EMBED>>>(gids);
    k_pred<<<NGRAPHS, OUTDIM>>>(pred_W, pred_b, out);
}

// round 2
// speedup vs baseline: 1.5873x; 1.5873x over previous
#include <cuda_runtime.h>

#define NNODES 100000
#define NEDGES 1000000
#define NGRAPHS 1000
#define EMBED 64
#define OUTDIM 128
#define NCONV 3
#define BN_EPS 1e-5f

#define SCAN_BLOCKS ((NNODES + 255) / 256)   // 391

// ---------------- scratch (no allocs allowed) ----------------
__device__ float d_h[NNODES * EMBED];      // node features (updated in place per layer)
__device__ float d_t[NNODES * EMBED];      // agg + h (GEMM input)
__device__ float d_y[NNODES * EMBED];      // GEMM output (pre-BN)
__device__ int   d_deg[NNODES];
__device__ int   d_rowptr[NNODES + 1];
__device__ int   d_cursor[NNODES];
__device__ int   d_bsum[512];
__device__ unsigned d_edge[NEDGES];        // packed: src (17 bits) | efeat << 17
__device__ float d_stats[NCONV * 2 * EMBED];  // per-layer [sum(64), sumsq(64)]
__device__ float d_gn[NGRAPHS * EMBED];

// ---------------- setup kernels ----------------
__global__ void k_zero() {
    int i = blockIdx.x * blockDim.x + threadIdx.x;
    if (i < NNODES) d_deg[i] = 0;
    if (i < NCONV * 2 * EMBED) d_stats[i] = 0.f;
}

__global__ void k_embed(const int* __restrict__ nfeat,
                        const float4* __restrict__ atom_embed) {
    int i = blockIdx.x * blockDim.x + threadIdx.x;   // float4 granularity
    if (i >= NNODES * (EMBED / 4)) return;
    int n = i >> 4;          // 16 float4 per row
    int c4 = i & 15;
    ((float4*)d_h)[i] = atom_embed[nfeat[n] * 16 + c4];
}

__global__ void k_count(const int* __restrict__ dst) {
    int e = blockIdx.x * blockDim.x + threadIdx.x;
    if (e < NEDGES) atomicAdd(&d_deg[dst[e]], 1);
}

// ---- 3-phase exclusive scan over deg -> rowptr ----
// Phase A: per-block (256-wide) scan; local exclusive prefix into rowptr,
// block total into d_bsum.
__global__ void k_scanA() {
    __shared__ int s[256];
    int t = threadIdx.x;
    int i = blockIdx.x * 256 + t;
    int v = (i < NNODES) ? d_deg[i] : 0;
    s[t] = v;
    __syncthreads();
    #pragma unroll
    for (int off = 1; off < 256; off <<= 1) {
        int u = (t >= off) ? s[t - off] : 0;
        __syncthreads();
        s[t] += u;
        __syncthreads();
    }
    if (i < NNODES) d_rowptr[i] = s[t] - v;   // local exclusive
    if (t == 255) d_bsum[blockIdx.x] = s[255];
}

// Phase B: single block scans the 391 block totals (exclusive).
__global__ void k_scanB() {
    __shared__ int s[512];
    int t = threadIdx.x;
    int v = (t < SCAN_BLOCKS) ? d_bsum[t] : 0;
    s[t] = v;
    __syncthreads();
    #pragma unroll
    for (int off = 1; off < 512; off <<= 1) {
        int u = (t >= off) ? s[t - off] : 0;
        __syncthreads();
        s[t] += u;
        __syncthreads();
    }
    if (t < SCAN_BLOCKS) d_bsum[t] = s[t] - v;      // exclusive block offset
    if (t == SCAN_BLOCKS - 1) d_rowptr[NNODES] = s[t];  // total = NEDGES
}

// Phase C: add block offsets, prime cursor.
__global__ void k_scanC() {
    int i = blockIdx.x * 256 + threadIdx.x;
    if (i >= NNODES) return;
    int r = d_rowptr[i] + d_bsum[blockIdx.x];
    d_rowptr[i] = r;
    d_cursor[i] = r;
}

__global__ void k_fill(const int* __restrict__ src,
                       const int* __restrict__ efeat,
                       const int* __restrict__ dst) {
    int e = blockIdx.x * blockDim.x + threadIdx.x;
    if (e >= NEDGES) return;
    int p = atomicAdd(&d_cursor[dst[e]], 1);
    d_edge[p] = (unsigned)src[e] | ((unsigned)efeat[e] << 17);
}

// ---------------- per-layer kernels ----------------
// warp per node: t[n] = mean_{e: dst=n} relu(bond[efeat] + h[src]) + h[n]
// 2x-unrolled edge loop for MLP.
__global__ void k_msg(const float* __restrict__ bond) {  // bond: [5,64] slice
    __shared__ __align__(16) float bsh[5 * EMBED];
    int tid = threadIdx.x;
    for (int i = tid; i < 5 * EMBED; i += blockDim.x) bsh[i] = bond[i];
    __syncthreads();
    int warp = tid >> 5, lane = tid & 31;
    int node = blockIdx.x * 8 + warp;
    if (node >= NNODES) return;
    int rs = d_rowptr[node], re = d_rowptr[node + 1];
    float ax = 0.f, ay = 0.f, bx = 0.f, by = 0.f;
    int e = rs;
    for (; e + 1 < re; e += 2) {
        unsigned p0 = d_edge[e], p1 = d_edge[e + 1];
        int s0 = (int)(p0 & 131071u), s1 = (int)(p1 & 131071u);
        int f0 = (int)(p0 >> 17),     f1 = (int)(p1 >> 17);
        float2 h0 = ((const float2*)(d_h + (size_t)s0 * EMBED))[lane];
        float2 h1 = ((const float2*)(d_h + (size_t)s1 * EMBED))[lane];
        float2 e0 = ((const float2*)(bsh + f0 * EMBED))[lane];
        float2 e1 = ((const float2*)(bsh + f1 * EMBED))[lane];
        ax += fmaxf(e0.x + h0.x, 0.f);
        ay += fmaxf(e0.y + h0.y, 0.f);
        bx += fmaxf(e1.x + h1.x, 0.f);
        by += fmaxf(e1.y + h1.y, 0.f);
    }
    if (e < re) {
        unsigned p0 = d_edge[e];
        int s0 = (int)(p0 & 131071u);
        int f0 = (int)(p0 >> 17);
        float2 h0 = ((const float2*)(d_h + (size_t)s0 * EMBED))[lane];
        float2 e0 = ((const float2*)(bsh + f0 * EMBED))[lane];
        ax += fmaxf(e0.x + h0.x, 0.f);
        ay += fmaxf(e0.y + h0.y, 0.f);
    }
    ax += bx; ay += by;
    int deg = re - rs;
    float inv = 1.f / (float)(deg > 0 ? deg : 1);
    float2 hn = ((const float2*)(d_h + (size_t)node * EMBED))[lane];
    float2 o;
    o.x = ax * inv + hn.x;
    o.y = ay * inv + hn.y;
    ((float2*)(d_t + (size_t)node * EMBED))[lane] = o;
}

// thread per node: y = t @ W + b  (W in shared as float4, t row in registers)
__global__ void k_gemm(const float* __restrict__ W, const float* __restrict__ b) {
    __shared__ float4 Ws[EMBED * 16];   // Ws[k*16 + c4]
    int tid = threadIdx.x;
    for (int i = tid; i < EMBED * 16; i += 256) Ws[i] = ((const float4*)W)[i];
    __syncthreads();
    int node = blockIdx.x * 256 + tid;
    if (node >= NNODES) return;
    float tr[EMBED];
    const float4* tp = (const float4*)(d_t + (size_t)node * EMBED);
    #pragma unroll
    for (int i = 0; i < 16; i++) {
        float4 v = tp[i];
        tr[4 * i] = v.x; tr[4 * i + 1] = v.y; tr[4 * i + 2] = v.z; tr[4 * i + 3] = v.w;
    }
    float4* yp = (float4*)(d_y + (size_t)node * EMBED);
    const float4* bp = (const float4*)b;
    for (int c4 = 0; c4 < 16; c4++) {
        float4 acc = bp[c4];
        #pragma unroll
        for (int k = 0; k < EMBED; k++) {
            float4 w = Ws[k * 16 + c4];
            float tk = tr[k];
            acc.x += tk * w.x; acc.y += tk * w.y;
            acc.z += tk * w.z; acc.w += tk * w.w;
        }
        yp[c4] = acc;
    }
}

// per-channel sum / sumsq over all nodes
__global__ void k_stats(int layer) {
    __shared__ float ssum[256], ssq[256];
    int tid = threadIdx.x;
    int c = tid & 63, grp = tid >> 6;   // 4 row-groups per block
    float sum = 0.f, sq = 0.f;
    for (int row = blockIdx.x * 4 + grp; row < NNODES; row += gridDim.x * 4) {
        float v = d_y[(size_t)row * EMBED + c];
        sum += v; sq += v * v;
    }
    ssum[tid] = sum; ssq[tid] = sq;
    __syncthreads();
    if (grp == 0) {
        sum = ssum[c] + ssum[64 + c] + ssum[128 + c] + ssum[192 + c];
        sq  = ssq[c]  + ssq[64 + c]  + ssq[128 + c]  + ssq[192 + c];
        atomicAdd(&d_stats[layer * 128 + c], sum);
        atomicAdd(&d_stats[layer * 128 + 64 + c], sq);
    }
}

// normalize + gamma/beta + optional relu + residual (h += act), float4 wide
__global__ void k_bn(int layer, const float* __restrict__ gamma,
                     const float* __restrict__ beta, int do_relu) {
    int i = blockIdx.x * blockDim.x + threadIdx.x;   // float4 index
    if (i >= NNODES * 16) return;
    int c4 = i & 15;
    const float* st = d_stats + layer * 128;
    const float invN = 1.f / (float)NNODES;
    float4 s1 = ((const float4*)st)[c4];
    float4 s2 = ((const float4*)(st + 64))[c4];
    float4 g  = ((const float4*)gamma)[c4];
    float4 be = ((const float4*)beta)[c4];
    float4 y  = ((const float4*)d_y)[i];
    float4 h  = ((const float4*)d_h)[i];
    float mu, var, rs, v;
    #define BN1(X) \
        mu = s1.X * invN; var = s2.X * invN - mu * mu; \
        rs = rsqrtf(fmaxf(var, 0.f) + BN_EPS); \
        v = (y.X - mu) * rs * g.X + be.X; \
        if (do_relu) v = fmaxf(v, 0.f); \
        h.X += v;
    BN1(x) BN1(y) BN1(z) BN1(w)
    #undef BN1
    ((float4*)d_h)[i] = h;
}

// ---------------- tail kernels ----------------
// block per graph; graph_ids sorted -> binary search range
__global__ void k_pool(const int* __restrict__ gids) {
    int g = blockIdx.x, c = threadIdx.x;
    int lo = 0, hi = NNODES;
    while (lo < hi) { int m = (lo + hi) >> 1; if (gids[m] < g) lo = m + 1; else hi = m; }
    int start = lo;
    hi = NNODES;
    while (lo < hi) { int m = (lo + hi) >> 1; if (gids[m] < g + 1) lo = m + 1; else hi = m; }
    int end = lo;
    float acc = 0.f, acc2 = 0.f;
    int n = start;
    for (; n + 1 < end; n += 2) {
        acc  += d_h[(size_t)n * EMBED + c];
        acc2 += d_h[(size_t)(n + 1) * EMBED + c];
    }
    if (n < end) acc += d_h[(size_t)n * EMBED + c];
    acc += acc2;
    int cnt = end - start;
    d_gn[g * EMBED + c] = acc / (float)(cnt > 0 ? cnt : 1);
}

__global__ void k_pred(const float* __restrict__ W, const float* __restrict__ b,
                       float* __restrict__ out) {
    __shared__ float gs[EMBED];
    int g = blockIdx.x, o = threadIdx.x;
    if (o < EMBED) gs[o] = d_gn[g * EMBED + o];
    __syncthreads();
    float acc = b[o];
    #pragma unroll
    for (int k = 0; k < EMBED; k++) acc += gs[k] * W[k * OUTDIM + o];
    out[g * OUTDIM + o] = acc;
}

// ---------------- launch ----------------
extern "C" void kernel_launch(void* const* d_in, const int* in_sizes, int n_in,
                              void* d_out, int out_size) {
    const int*   nfeat      = (const int*)d_in[0];
    const int*   efeat      = (const int*)d_in[1];
    const int*   src        = (const int*)d_in[2];
    const int*   dst        = (const int*)d_in[3];
    const int*   gids       = (const int*)d_in[4];
    const float* atom_embed = (const float*)d_in[5];
    const float* bond_embed = (const float*)d_in[6];
    const float* conv_W     = (const float*)d_in[7];
    const float* conv_b     = (const float*)d_in[8];
    const float* bn_gamma   = (const float*)d_in[9];
    const float* bn_beta    = (const float*)d_in[10];
    const float* pred_W     = (const float*)d_in[11];
    const float* pred_b     = (const float*)d_in[12];
    float* out = (float*)d_out;

    k_zero<<<(NNODES + 255) / 256, 256>>>();
    k_embed<<<(NNODES * 16 + 255) / 256, 256>>>(nfeat, (const float4*)atom_embed);
    k_count<<<(NEDGES + 255) / 256, 256>>>(dst);
    k_scanA<<<SCAN_BLOCKS, 256>>>();
    k_scanB<<<1, 512>>>();
    k_scanC<<<SCAN_BLOCKS, 256>>>();
    k_fill<<<(NEDGES + 255) / 256, 256>>>(src, efeat, dst);

    for (int i = 0; i < NCONV; i++) {
        k_msg<<<(NNODES + 7) / 8, 256>>>(bond_embed + i * 5 * EMBED);
        k_gemm<<<(NNODES + 255) / 256, 256>>>(conv_W + i * EMBED * EMBED,
                                              conv_b + i * EMBED);
        k_stats<<<256, 256>>>(i);
        k_bn<<<(NNODES * 16 + 255) / 256, 256>>>(i, bn_gamma + i * EMBED,
                                                 bn_beta + i * EMBED,
                                                 (i < NCONV - 1) ? 1 : 0);
    }

    k_pool<<<NGRAPHS, EMBED>>>(gids);
    k_pred<<<NGRAPHS, OUTDIM>>>(pred_W, pred_b, out);
}

// round 4
// speedup vs baseline: 1.6353x; 1.0302x over previous
#include <cuda_runtime.h>

#define NNODES 100000
#define NEDGES 1000000
#define NGRAPHS 1000
#define EMBED 64
#define OUTDIM 128
#define NCONV 3
#define BN_EPS 1e-5f

#define SCAN_BLOCKS ((NNODES + 255) / 256)   // 391

typedef unsigned long long u64;

// ---------------- scratch (no allocs allowed) ----------------
// NOTE: stats MUST be 16B-aligned (float4 loads in k_bn) -> placed first.
struct alignas(16) ZBuf {     // zeroed via one cudaMemsetAsync each call
    float stats[NCONV * 2 * EMBED];   // offset 0, 1536 B (mult of 16)
    int   deg[NNODES];
    int   cnt;                // scan arrival counter
    int   done;               // scan completion flag
};
__device__ ZBuf d_Z;

__device__ float d_h[NNODES * EMBED];      // node features
__device__ float d_t[NNODES * EMBED];      // agg + h (GEMM input)
__device__ float d_y[NNODES * EMBED];      // GEMM output (pre-BN)
__device__ int   d_rowptr[NNODES + 1];
__device__ int   d_cursor[NNODES];
__device__ int   d_aggr[512];
__device__ int   d_off[512];
__device__ unsigned d_edge[NEDGES];        // packed: src (17 bits) | efeat << 17
__device__ float d_gn[NGRAPHS * EMBED];

// ---------------- f32x2 helpers ----------------
__device__ __forceinline__ u64 ffma2(u64 a, u64 b, u64 c) {
    u64 d;
    asm("fma.rn.f32x2 %0, %1, %2, %3;" : "=l"(d) : "l"(a), "l"(b), "l"(c));
    return d;
}
__device__ __forceinline__ u64 pack2(float x) {
    u64 d;
    asm("mov.b64 %0, {%1, %1};" : "=l"(d) : "f"(x));
    return d;
}

// ---------------- setup kernels ----------------
// embed (1.6M float4 threads) + degree count (first 1M threads)
__global__ void k_embed_count(const int* __restrict__ nfeat,
                              const float4* __restrict__ atom_embed,
                              const int* __restrict__ dst) {
    int i = blockIdx.x * 256 + threadIdx.x;
    if (i < NNODES * 16) {
        int n = i >> 4, c4 = i & 15;
        ((float4*)d_h)[i] = atom_embed[nfeat[n] * 16 + c4];
    }
    if (i < NEDGES) atomicAdd(&d_Z.deg[dst[i]], 1);
}

// single-kernel exclusive scan: block-local scan, last-arriving block computes
// the 391 block offsets, everyone else spins. 391 blocks are all resident
// (capacity >= 4/SM at 256 thr / tiny smem) so the spin cannot deadlock.
__global__ void k_scan() {
    __shared__ int s[256];
    __shared__ int s2[256];
    __shared__ int sdone;
    int t = threadIdx.x, bid = blockIdx.x;
    int i = bid * 256 + t;
    int v = (i < NNODES) ? d_Z.deg[i] : 0;
    s[t] = v;
    __syncthreads();
    #pragma unroll
    for (int off = 1; off < 256; off <<= 1) {
        int u = (t >= off) ? s[t - off] : 0;
        __syncthreads();
        s[t] += u;
        __syncthreads();
    }
    int lexcl = s[t] - v;      // local exclusive prefix
    int agg = s[255];
    if (t == 0) {
        d_aggr[bid] = agg;
        __threadfence();
        int old = atomicAdd(&d_Z.cnt, 1);
        sdone = (old == SCAN_BLOCKS - 1);
    }
    __syncthreads();
    if (sdone) {
        // this (last-arriving) block scans the block aggregates: 2 per thread
        int a0 = (2 * t < SCAN_BLOCKS) ? d_aggr[2 * t] : 0;
        int a1 = (2 * t + 1 < SCAN_BLOCKS) ? d_aggr[2 * t + 1] : 0;
        s2[t] = a0 + a1;
        __syncthreads();
        #pragma unroll
        for (int off = 1; off < 256; off <<= 1) {
            int u = (t >= off) ? s2[t - off] : 0;
            __syncthreads();
            s2[t] += u;
            __syncthreads();
        }
        int ex = s2[t] - (a0 + a1);
        d_off[2 * t] = ex;
        d_off[2 * t + 1] = ex + a0;
        if (t == 255) d_rowptr[NNODES] = s2[255];
        __threadfence();
        if (t == 0) atomicExch(&d_Z.done, 1);
    }
    if (t == 0) {
        while (atomicAdd(&d_Z.done, 0) == 0) __nanosleep(40);
    }
    __syncthreads();
    int boff = __ldcg(&d_off[bid]);    // bypass L1 (written by another block)
    if (i < NNODES) {
        int r = lexcl + boff;
        d_rowptr[i] = r;
        d_cursor[i] = r;
    }
}

__global__ void k_fill(const int* __restrict__ src,
                       const int* __restrict__ efeat,
                       const int* __restrict__ dst) {
    int e = blockIdx.x * blockDim.x + threadIdx.x;
    if (e >= NEDGES) return;
    int p = atomicAdd(&d_cursor[dst[e]], 1);
    d_edge[p] = (unsigned)src[e] | ((unsigned)efeat[e] << 17);
}

// ---------------- per-layer kernels ----------------
// warp per node: t[n] = mean_{e: dst=n} relu(bond[efeat] + h[src]) + h[n]
// 4x-unrolled edge loop for MLP.
__global__ void k_msg(const float* __restrict__ bond) {  // bond: [5,64] slice
    __shared__ __align__(16) float bsh[5 * EMBED];
    int tid = threadIdx.x;
    for (int i = tid; i < 5 * EMBED; i += 256) bsh[i] = bond[i];
    __syncthreads();
    int warp = tid >> 5, lane = tid & 31;
    int node = blockIdx.x * 8 + warp;
    if (node >= NNODES) return;
    int rs = d_rowptr[node], re = d_rowptr[node + 1];
    float ax = 0.f, ay = 0.f, bx = 0.f, by = 0.f;
    float cx = 0.f, cy = 0.f, dx = 0.f, dy = 0.f;
    int e = rs;
    for (; e + 3 < re; e += 4) {
        unsigned p0 = d_edge[e],     p1 = d_edge[e + 1];
        unsigned p2 = d_edge[e + 2], p3 = d_edge[e + 3];
        float2 h0 = ((const float2*)(d_h + (size_t)(p0 & 131071u) * EMBED))[lane];
        float2 h1 = ((const float2*)(d_h + (size_t)(p1 & 131071u) * EMBED))[lane];
        float2 h2 = ((const float2*)(d_h + (size_t)(p2 & 131071u) * EMBED))[lane];
        float2 h3 = ((const float2*)(d_h + (size_t)(p3 & 131071u) * EMBED))[lane];
        float2 e0 = ((const float2*)(bsh + (p0 >> 17) * EMBED))[lane];
        float2 e1 = ((const float2*)(bsh + (p1 >> 17) * EMBED))[lane];
        float2 e2 = ((const float2*)(bsh + (p2 >> 17) * EMBED))[lane];
        float2 e3 = ((const float2*)(bsh + (p3 >> 17) * EMBED))[lane];
        ax += fmaxf(e0.x + h0.x, 0.f);  ay += fmaxf(e0.y + h0.y, 0.f);
        bx += fmaxf(e1.x + h1.x, 0.f);  by += fmaxf(e1.y + h1.y, 0.f);
        cx += fmaxf(e2.x + h2.x, 0.f);  cy += fmaxf(e2.y + h2.y, 0.f);
        dx += fmaxf(e3.x + h3.x, 0.f);  dy += fmaxf(e3.y + h3.y, 0.f);
    }
    for (; e < re; e++) {
        unsigned p0 = d_edge[e];
        float2 h0 = ((const float2*)(d_h + (size_t)(p0 & 131071u) * EMBED))[lane];
        float2 e0 = ((const float2*)(bsh + (p0 >> 17) * EMBED))[lane];
        ax += fmaxf(e0.x + h0.x, 0.f);  ay += fmaxf(e0.y + h0.y, 0.f);
    }
    ax += bx + cx + dx;
    ay += by + cy + dy;
    int deg = re - rs;
    float inv = 1.f / (float)(deg > 0 ? deg : 1);
    float2 hn = ((const float2*)(d_h + (size_t)node * EMBED))[lane];
    float2 o;
    o.x = ax * inv + hn.x;
    o.y = ay * inv + hn.y;
    ((float2*)(d_t + (size_t)node * EMBED))[lane] = o;
}

// thread per node: y = t @ W + b, packed f32x2 FMA, all 64 outputs live.
__global__ void __launch_bounds__(256) k_gemm(const float* __restrict__ W,
                                              const float* __restrict__ b) {
    __shared__ ulonglong2 Ws[EMBED * 16];   // Ws[k*16 + c8] = channels 8c8.. of row k
    int tid = threadIdx.x;
    for (int i = tid; i < EMBED * 16; i += 256) Ws[i] = ((const ulonglong2*)W)[i];
    __syncthreads();
    int node = blockIdx.x * 256 + tid;
    if (node >= NNODES) return;
    u64 acc[32];
    const u64* bp = (const u64*)b;
    #pragma unroll
    for (int i = 0; i < 32; i++) acc[i] = bp[i];
    const float4* tp = (const float4*)(d_t + (size_t)node * EMBED);
    #pragma unroll 1
    for (int k4 = 0; k4 < 16; k4++) {
        float4 tv = tp[k4];
        #pragma unroll
        for (int j = 0; j < 4; j++) {
            float tk = (j == 0) ? tv.x : (j == 1) ? tv.y : (j == 2) ? tv.z : tv.w;
            u64 tkk = pack2(tk);
            int k = k4 * 4 + j;
            #pragma unroll
            for (int c8 = 0; c8 < 16; c8++) {
                ulonglong2 w = Ws[k * 16 + c8];
                acc[2 * c8]     = ffma2(tkk, w.x, acc[2 * c8]);
                acc[2 * c8 + 1] = ffma2(tkk, w.y, acc[2 * c8 + 1]);
            }
        }
    }
    ulonglong2* yp = (ulonglong2*)(d_y + (size_t)node * EMBED);
    #pragma unroll
    for (int i = 0; i < 16; i++)
        yp[i] = make_ulonglong2(acc[2 * i], acc[2 * i + 1]);
}

// per-channel sum / sumsq over all nodes
__global__ void k_stats(int layer) {
    __shared__ float ssum[256], ssq[256];
    int tid = threadIdx.x;
    int c = tid & 63, grp = tid >> 6;   // 4 row-groups per block
    float sum = 0.f, sq = 0.f;
    for (int row = blockIdx.x * 4 + grp; row < NNODES; row += gridDim.x * 4) {
        float v = d_y[(size_t)row * EMBED + c];
        sum += v; sq += v * v;
    }
    ssum[tid] = sum; ssq[tid] = sq;
    __syncthreads();
    if (grp == 0) {
        sum = ssum[c] + ssum[64 + c] + ssum[128 + c] + ssum[192 + c];
        sq  = ssq[c]  + ssq[64 + c]  + ssq[128 + c]  + ssq[192 + c];
        atomicAdd(&d_Z.stats[layer * 128 + c], sum);
        atomicAdd(&d_Z.stats[layer * 128 + 64 + c], sq);
    }
}

// normalize + gamma/beta + optional relu + residual (h += act), float4 wide
__global__ void k_bn(int layer, const float* __restrict__ gamma,
                     const float* __restrict__ beta, int do_relu) {
    int i = blockIdx.x * blockDim.x + threadIdx.x;   // float4 index
    if (i >= NNODES * 16) return;
    int c4 = i & 15;
    const float* st = d_Z.stats + layer * 128;   // 16B-aligned (stats at struct start)
    const float invN = 1.f / (float)NNODES;
    float4 s1 = ((const float4*)st)[c4];
    float4 s2 = ((const float4*)(st + 64))[c4];
    float4 g  = ((const float4*)gamma)[c4];
    float4 be = ((const float4*)beta)[c4];
    float4 y  = ((const float4*)d_y)[i];
    float4 h  = ((const float4*)d_h)[i];
    float mu, var, rs, v;
    #define BN1(X) \
        mu = s1.X * invN; var = s2.X * invN - mu * mu; \
        rs = rsqrtf(fmaxf(var, 0.f) + BN_EPS); \
        v = (y.X - mu) * rs * g.X + be.X; \
        if (do_relu) v = fmaxf(v, 0.f); \
        h.X += v;
    BN1(x) BN1(y) BN1(z) BN1(w)
    #undef BN1
    ((float4*)d_h)[i] = h;
}

// ---------------- tail kernels ----------------
// block per graph; 64 channels x 4 row-groups for MLP
__global__ void k_pool(const int* __restrict__ gids) {
    __shared__ float red[256];
    __shared__ int range[2];
    int g = blockIdx.x, tid = threadIdx.x;
    int c = tid & 63, grp = tid >> 6;
    if (tid < 2) {
        int target = g + tid;   // lower_bound(g), lower_bound(g+1)
        int lo = 0, hi = NNODES;
        while (lo < hi) { int m = (lo + hi) >> 1; if (gids[m] < target) lo = m + 1; else hi = m; }
        range[tid] = lo;
    }
    __syncthreads();
    int start = range[0], end = range[1];
    float acc = 0.f;
    for (int n = start + grp; n < end; n += 4)
        acc += d_h[(size_t)n * EMBED + c];
    red[tid] = acc;
    __syncthreads();
    if (grp == 0) {
        float s = red[c] + red[64 + c] + red[128 + c] + red[192 + c];
        int cnt = end - start;
        d_gn[g * EMBED + c] = s / (float)(cnt > 0 ? cnt : 1);
    }
}

__global__ void k_pred(const float* __restrict__ W, const float* __restrict__ b,
                       float* __restrict__ out) {
    __shared__ float gs[EMBED];
    int g = blockIdx.x, o = threadIdx.x;
    if (o < EMBED) gs[o] = d_gn[g * EMBED + o];
    __syncthreads();
    float acc = b[o];
    #pragma unroll
    for (int k = 0; k < EMBED; k++) acc += gs[k] * W[k * OUTDIM + o];
    out[g * OUTDIM + o] = acc;
}

// ---------------- launch ----------------
extern "C" void kernel_launch(void* const* d_in, const int* in_sizes, int n_in,
                              void* d_out, int out_size) {
    const int*   nfeat      = (const int*)d_in[0];
    const int*   efeat      = (const int*)d_in[1];
    const int*   src        = (const int*)d_in[2];
    const int*   dst        = (const int*)d_in[3];
    const int*   gids       = (const int*)d_in[4];
    const float* atom_embed = (const float*)d_in[5];
    const float* bond_embed = (const float*)d_in[6];
    const float* conv_W     = (const float*)d_in[7];
    const float* conv_b     = (const float*)d_in[8];
    const float* bn_gamma   = (const float*)d_in[9];
    const float* bn_beta    = (const float*)d_in[10];
    const float* pred_W     = (const float*)d_in[11];
    const float* pred_b     = (const float*)d_in[12];
    float* out = (float*)d_out;

    void* zp = nullptr;
    cudaGetSymbolAddress(&zp, d_Z);
    cudaMemsetAsync(zp, 0, sizeof(ZBuf), 0);

    k_embed_count<<<(NNODES * 16 + 255) / 256, 256>>>(nfeat, (const float4*)atom_embed, dst);
    k_scan<<<SCAN_BLOCKS, 256>>>();
    k_fill<<<(NEDGES + 255) / 256, 256>>>(src, efeat, dst);

    for (int i = 0; i < NCONV; i++) {
        k_msg<<<(NNODES + 7) / 8, 256>>>(bond_embed + i * 5 * EMBED);
        k_gemm<<<(NNODES + 255) / 256, 256>>>(conv_W + i * EMBED * EMBED,
                                              conv_b + i * EMBED);
        k_stats<<<256, 256>>>(i);
        k_bn<<<(NNODES * 16 + 255) / 256, 256>>>(i, bn_gamma + i * EMBED,
                                                 bn_beta + i * EMBED,
                                                 (i < NCONV - 1) ? 1 : 0);
    }

    k_pool<<<NGRAPHS, 256>>>(gids);
    k_pred<<<NGRAPHS, OUTDIM>>>(pred_W, pred_b, out);
}

// round 5
// speedup vs baseline: 1.7759x; 1.0860x over previous
#include <cuda_runtime.h>

#define NNODES 100000
#define NEDGES 1000000
#define NGRAPHS 1000
#define EMBED 64
#define OUTDIM 128
#define NCONV 3
#define BN_EPS 1e-5f

#define SCAN_BLOCKS ((NNODES + 255) / 256)   // 391

typedef unsigned long long u64;

// ---------------- scratch (no allocs allowed) ----------------
// stats MUST be 16B-aligned (float4 loads in k_bn) -> placed first.
struct alignas(16) ZBuf {     // zeroed via one cudaMemsetAsync each call
    float stats[NCONV * 2 * EMBED];   // offset 0, 1536 B (mult of 16)
    int   deg[NNODES];
    int   cnt;                // scan arrival counter
    int   done;               // scan completion flag
};
__device__ ZBuf d_Z;

__device__ float d_h[NNODES * EMBED];      // node features
__device__ float d_t[NNODES * EMBED];      // agg + h (GEMM input)
__device__ float d_y[NNODES * EMBED];      // GEMM output (pre-BN)
__device__ int   d_rowptr[NNODES + 1];
__device__ int   d_cursor[NNODES];
__device__ int   d_aggr[512];
__device__ int   d_off[512];
__device__ unsigned d_edge[NEDGES];        // packed: (src << 8) | efeat
__device__ float d_gn[NGRAPHS * EMBED];

// ---------------- f32x2 helpers ----------------
__device__ __forceinline__ u64 ffma2(u64 a, u64 b, u64 c) {
    u64 d;
    asm("fma.rn.f32x2 %0, %1, %2, %3;" : "=l"(d) : "l"(a), "l"(b), "l"(c));
    return d;
}
__device__ __forceinline__ u64 pack2(float x) {
    u64 d;
    asm("mov.b64 %0, {%1, %1};" : "=l"(d) : "f"(x));
    return d;
}

// ---------------- setup kernels ----------------
// embed (1.6M float4 threads) + degree count (first 1M threads)
__global__ void k_embed_count(const int* __restrict__ nfeat,
                              const float4* __restrict__ atom_embed,
                              const int* __restrict__ dst) {
    int i = blockIdx.x * 256 + threadIdx.x;
    if (i < NNODES * 16) {
        int n = i >> 4, c4 = i & 15;
        ((float4*)d_h)[i] = atom_embed[nfeat[n] * 16 + c4];
    }
    if (i < NEDGES) atomicAdd(&d_Z.deg[dst[i]], 1);
}

// single-kernel exclusive scan: block-local scan, last-arriving block computes
// the 391 block offsets, everyone else spins. 391 blocks all resident -> safe.
__global__ void k_scan() {
    __shared__ int s[256];
    __shared__ int s2[256];
    __shared__ int sdone;
    int t = threadIdx.x, bid = blockIdx.x;
    int i = bid * 256 + t;
    int v = (i < NNODES) ? d_Z.deg[i] : 0;
    s[t] = v;
    __syncthreads();
    #pragma unroll
    for (int off = 1; off < 256; off <<= 1) {
        int u = (t >= off) ? s[t - off] : 0;
        __syncthreads();
        s[t] += u;
        __syncthreads();
    }
    int lexcl = s[t] - v;      // local exclusive prefix
    int agg = s[255];
    if (t == 0) {
        d_aggr[bid] = agg;
        __threadfence();
        int old = atomicAdd(&d_Z.cnt, 1);
        sdone = (old == SCAN_BLOCKS - 1);
    }
    __syncthreads();
    if (sdone) {
        int a0 = (2 * t < SCAN_BLOCKS) ? d_aggr[2 * t] : 0;
        int a1 = (2 * t + 1 < SCAN_BLOCKS) ? d_aggr[2 * t + 1] : 0;
        s2[t] = a0 + a1;
        __syncthreads();
        #pragma unroll
        for (int off = 1; off < 256; off <<= 1) {
            int u = (t >= off) ? s2[t - off] : 0;
            __syncthreads();
            s2[t] += u;
            __syncthreads();
        }
        int ex = s2[t] - (a0 + a1);
        d_off[2 * t] = ex;
        d_off[2 * t + 1] = ex + a0;
        if (t == 255) d_rowptr[NNODES] = s2[255];
        __threadfence();
        if (t == 0) atomicExch(&d_Z.done, 1);
    }
    if (t == 0) {
        while (atomicAdd(&d_Z.done, 0) == 0) __nanosleep(40);
    }
    __syncthreads();
    int boff = __ldcg(&d_off[bid]);
    if (i < NNODES) {
        int r = lexcl + boff;
        d_rowptr[i] = r;
        d_cursor[i] = r;
    }
}

__global__ void k_fill(const int* __restrict__ src,
                       const int* __restrict__ efeat,
                       const int* __restrict__ dst) {
    int e = blockIdx.x * blockDim.x + threadIdx.x;
    if (e >= NEDGES) return;
    int p = atomicAdd(&d_cursor[dst[e]], 1);
    d_edge[p] = ((unsigned)src[e] << 8) | (unsigned)efeat[e];
}

// ---------------- per-layer kernels ----------------
// 2 nodes per warp: lanes 0-15 -> node A, lanes 16-31 -> node B.
// Each lane covers 4 channels (float4): one LDG.128 gathers an h-row
// for TWO edges at once. t[n] = mean_e relu(bond[ef] + h[src]) + h[n].
__global__ void __launch_bounds__(256) k_msg(const float* __restrict__ bond) {
    __shared__ __align__(16) float4 bsh[5 * 16];
    int tid = threadIdx.x;
    if (tid < 80) bsh[tid] = ((const float4*)bond)[tid];
    __syncthreads();
    int warp = tid >> 5, lane = tid & 31;
    int half = lane >> 4, hl = lane & 15;
    int node = blockIdx.x * 16 + warp * 2 + half;
    int rs = 0, re = 0;
    if (node < NNODES) { rs = d_rowptr[node]; re = d_rowptr[node + 1]; }
    int cnt = re - rs;
    int ocnt = __shfl_xor_sync(0xffffffffu, cnt, 16);
    int mn = min(cnt, ocnt) & ~3;       // unpredicated main loop bound
    int mx = max(cnt, ocnt);            // ragged tail bound
    const char* hbase = (const char*)d_h + hl * 16;
    const char* bbase = (const char*)bsh + hl * 16;
    float4 s0 = make_float4(0.f, 0.f, 0.f, 0.f), s1 = s0, s2 = s0, s3 = s0;
    int i = 0;
    for (; i < mn; i += 4) {
        unsigned p0 = d_edge[rs + i],     p1 = d_edge[rs + i + 1];
        unsigned p2 = d_edge[rs + i + 2], p3 = d_edge[rs + i + 3];
        float4 h0 = *(const float4*)(hbase + (p0 & 0xFFFFFF00u));
        float4 h1 = *(const float4*)(hbase + (p1 & 0xFFFFFF00u));
        float4 h2 = *(const float4*)(hbase + (p2 & 0xFFFFFF00u));
        float4 h3 = *(const float4*)(hbase + (p3 & 0xFFFFFF00u));
        float4 b0 = *(const float4*)(bbase + ((p0 & 255u) << 8));
        float4 b1 = *(const float4*)(bbase + ((p1 & 255u) << 8));
        float4 b2 = *(const float4*)(bbase + ((p2 & 255u) << 8));
        float4 b3 = *(const float4*)(bbase + ((p3 & 255u) << 8));
        s0.x += fmaxf(b0.x + h0.x, 0.f); s0.y += fmaxf(b0.y + h0.y, 0.f);
        s0.z += fmaxf(b0.z + h0.z, 0.f); s0.w += fmaxf(b0.w + h0.w, 0.f);
        s1.x += fmaxf(b1.x + h1.x, 0.f); s1.y += fmaxf(b1.y + h1.y, 0.f);
        s1.z += fmaxf(b1.z + h1.z, 0.f); s1.w += fmaxf(b1.w + h1.w, 0.f);
        s2.x += fmaxf(b2.x + h2.x, 0.f); s2.y += fmaxf(b2.y + h2.y, 0.f);
        s2.z += fmaxf(b2.z + h2.z, 0.f); s2.w += fmaxf(b2.w + h2.w, 0.f);
        s3.x += fmaxf(b3.x + h3.x, 0.f); s3.y += fmaxf(b3.y + h3.y, 0.f);
        s3.z += fmaxf(b3.z + h3.z, 0.f); s3.w += fmaxf(b3.w + h3.w, 0.f);
    }
    for (; i < mx; i++) {
        if (i < cnt) {
            unsigned p = d_edge[rs + i];
            float4 hh = *(const float4*)(hbase + (p & 0xFFFFFF00u));
            float4 bb = *(const float4*)(bbase + ((p & 255u) << 8));
            s0.x += fmaxf(bb.x + hh.x, 0.f); s0.y += fmaxf(bb.y + hh.y, 0.f);
            s0.z += fmaxf(bb.z + hh.z, 0.f); s0.w += fmaxf(bb.w + hh.w, 0.f);
        }
    }
    if (node < NNODES) {
        float inv = 1.f / (float)(cnt > 0 ? cnt : 1);
        float4 hn = ((const float4*)(d_h + (size_t)node * EMBED))[hl];
        float4 o;
        o.x = (s0.x + s1.x + s2.x + s3.x) * inv + hn.x;
        o.y = (s0.y + s1.y + s2.y + s3.y) * inv + hn.y;
        o.z = (s0.z + s1.z + s2.z + s3.z) * inv + hn.z;
        o.w = (s0.w + s1.w + s2.w + s3.w) * inv + hn.w;
        ((float4*)(d_t + (size_t)node * EMBED))[hl] = o;
    }
}

// thread per node: y = t @ W + b, packed f32x2 FMA, all 64 outputs live.
__global__ void __launch_bounds__(256) k_gemm(const float* __restrict__ W,
                                              const float* __restrict__ b) {
    __shared__ ulonglong2 Ws[EMBED * 16];
    int tid = threadIdx.x;
    for (int i = tid; i < EMBED * 16; i += 256) Ws[i] = ((const ulonglong2*)W)[i];
    __syncthreads();
    int node = blockIdx.x * 256 + tid;
    if (node >= NNODES) return;
    u64 acc[32];
    const u64* bp = (const u64*)b;
    #pragma unroll
    for (int i = 0; i < 32; i++) acc[i] = bp[i];
    const float4* tp = (const float4*)(d_t + (size_t)node * EMBED);
    #pragma unroll 1
    for (int k4 = 0; k4 < 16; k4++) {
        float4 tv = tp[k4];
        #pragma unroll
        for (int j = 0; j < 4; j++) {
            float tk = (j == 0) ? tv.x : (j == 1) ? tv.y : (j == 2) ? tv.z : tv.w;
            u64 tkk = pack2(tk);
            int k = k4 * 4 + j;
            #pragma unroll
            for (int c8 = 0; c8 < 16; c8++) {
                ulonglong2 w = Ws[k * 16 + c8];
                acc[2 * c8]     = ffma2(tkk, w.x, acc[2 * c8]);
                acc[2 * c8 + 1] = ffma2(tkk, w.y, acc[2 * c8 + 1]);
            }
        }
    }
    ulonglong2* yp = (ulonglong2*)(d_y + (size_t)node * EMBED);
    #pragma unroll
    for (int i = 0; i < 16; i++)
        yp[i] = make_ulonglong2(acc[2 * i], acc[2 * i + 1]);
}

// per-channel sum / sumsq over all nodes, float4-wide
__global__ void k_stats(int layer) {
    __shared__ float4 ssum[256], ssq[256];
    int tid = threadIdx.x;
    int c4 = tid & 15, grp = tid >> 4;   // 16 row-groups of 16 float4-channels
    float4 sum = make_float4(0.f, 0.f, 0.f, 0.f), sq = sum;
    for (int row = blockIdx.x * 16 + grp; row < NNODES; row += gridDim.x * 16) {
        float4 v = ((const float4*)d_y)[row * 16 + c4];
        sum.x += v.x; sum.y += v.y; sum.z += v.z; sum.w += v.w;
        sq.x += v.x * v.x; sq.y += v.y * v.y; sq.z += v.z * v.z; sq.w += v.w * v.w;
    }
    ssum[tid] = sum; ssq[tid] = sq;
    __syncthreads();
    if (grp == 0) {
        #pragma unroll
        for (int g = 1; g < 16; g++) {
            float4 a = ssum[g * 16 + c4], q = ssq[g * 16 + c4];
            sum.x += a.x; sum.y += a.y; sum.z += a.z; sum.w += a.w;
            sq.x += q.x; sq.y += q.y; sq.z += q.z; sq.w += q.w;
        }
        float* st = d_Z.stats + layer * 128;
        atomicAdd(&st[c4 * 4 + 0], sum.x);
        atomicAdd(&st[c4 * 4 + 1], sum.y);
        atomicAdd(&st[c4 * 4 + 2], sum.z);
        atomicAdd(&st[c4 * 4 + 3], sum.w);
        atomicAdd(&st[64 + c4 * 4 + 0], sq.x);
        atomicAdd(&st[64 + c4 * 4 + 1], sq.y);
        atomicAdd(&st[64 + c4 * 4 + 2], sq.z);
        atomicAdd(&st[64 + c4 * 4 + 3], sq.w);
    }
}

// normalize + gamma/beta + optional relu + residual (h += act), float4 wide
__global__ void k_bn(int layer, const float* __restrict__ gamma,
                     const float* __restrict__ beta, int do_relu) {
    int i = blockIdx.x * blockDim.x + threadIdx.x;   // float4 index
    if (i >= NNODES * 16) return;
    int c4 = i & 15;
    const float* st = d_Z.stats + layer * 128;
    const float invN = 1.f / (float)NNODES;
    float4 s1 = ((const float4*)st)[c4];
    float4 s2 = ((const float4*)(st + 64))[c4];
    float4 g  = ((const float4*)gamma)[c4];
    float4 be = ((const float4*)beta)[c4];
    float4 y  = ((const float4*)d_y)[i];
    float4 h  = ((const float4*)d_h)[i];
    float mu, var, rs, v;
    #define BN1(X) \
        mu = s1.X * invN; var = s2.X * invN - mu * mu; \
        rs = rsqrtf(fmaxf(var, 0.f) + BN_EPS); \
        v = (y.X - mu) * rs * g.X + be.X; \
        if (do_relu) v = fmaxf(v, 0.f); \
        h.X += v;
    BN1(x) BN1(y) BN1(z) BN1(w)
    #undef BN1
    ((float4*)d_h)[i] = h;
}

// ---------------- tail kernels ----------------
__global__ void k_pool(const int* __restrict__ gids) {
    __shared__ float red[256];
    __shared__ int range[2];
    int g = blockIdx.x, tid = threadIdx.x;
    int c = tid & 63, grp = tid >> 6;
    if (tid < 2) {
        int target = g + tid;
        int lo = 0, hi = NNODES;
        while (lo < hi) { int m = (lo + hi) >> 1; if (gids[m] < target) lo = m + 1; else hi = m; }
        range[tid] = lo;
    }
    __syncthreads();
    int start = range[0], end = range[1];
    float acc = 0.f;
    for (int n = start + grp; n < end; n += 4)
        acc += d_h[(size_t)n * EMBED + c];
    red[tid] = acc;
    __syncthreads();
    if (grp == 0) {
        float s = red[c] + red[64 + c] + red[128 + c] + red[192 + c];
        int cntg = end - start;
        d_gn[g * EMBED + c] = s / (float)(cntg > 0 ? cntg : 1);
    }
}

__global__ void k_pred(const float* __restrict__ W, const float* __restrict__ b,
                       float* __restrict__ out) {
    __shared__ float gs[EMBED];
    int g = blockIdx.x, o = threadIdx.x;
    if (o < EMBED) gs[o] = d_gn[g * EMBED + o];
    __syncthreads();
    float acc = b[o];
    #pragma unroll
    for (int k = 0; k < EMBED; k++) acc += gs[k] * W[k * OUTDIM + o];
    out[g * OUTDIM + o] = acc;
}

// ---------------- launch ----------------
extern "C" void kernel_launch(void* const* d_in, const int* in_sizes, int n_in,
                              void* d_out, int out_size) {
    const int*   nfeat      = (const int*)d_in[0];
    const int*   efeat      = (const int*)d_in[1];
    const int*   src        = (const int*)d_in[2];
    const int*   dst        = (const int*)d_in[3];
    const int*   gids       = (const int*)d_in[4];
    const float* atom_embed = (const float*)d_in[5];
    const float* bond_embed = (const float*)d_in[6];
    const float* conv_W     = (const float*)d_in[7];
    const float* conv_b     = (const float*)d_in[8];
    const float* bn_gamma   = (const float*)d_in[9];
    const float* bn_beta    = (const float*)d_in[10];
    const float* pred_W     = (const float*)d_in[11];
    const float* pred_b     = (const float*)d_in[12];
    float* out = (float*)d_out;

    void* zp = nullptr;
    cudaGetSymbolAddress(&zp, d_Z);
    cudaMemsetAsync(zp, 0, sizeof(ZBuf), 0);

    k_embed_count<<<(NNODES * 16 + 255) / 256, 256>>>(nfeat, (const float4*)atom_embed, dst);
    k_scan<<<SCAN_BLOCKS, 256>>>();
    k_fill<<<(NEDGES + 255) / 256, 256>>>(src, efeat, dst);

    for (int i = 0; i < NCONV; i++) {
        k_msg<<<(NNODES + 15) / 16, 256>>>(bond_embed + i * 5 * EMBED);
        k_gemm<<<(NNODES + 255) / 256, 256>>>(conv_W + i * EMBED * EMBED,
                                              conv_b + i * EMBED);
        k_stats<<<256, 256>>>(i);
        k_bn<<<(NNODES * 16 + 255) / 256, 256>>>(i, bn_gamma + i * EMBED,
                                                 bn_beta + i * EMBED,
                                                 (i < NCONV - 1) ? 1 : 0);
    }

    k_pool<<<NGRAPHS, 256>>>(gids);
    k_pred<<<NGRAPHS, OUTDIM>>>(pred_W, pred_b, out);
}